// round 15
// baseline (speedup 1.0000x reference)
#include <cuda_runtime.h>
#include <cuda_fp16.h>
#include <cstdint>

#define NB 2
#define NS 2048
#define NE 1024
#define NH 16
#define ND 64
#define NM (NB*NS)      // 4096 rows
#define NHD (NH*ND)     // 1024

// ---------------------------------------------------------------------------
// Scratch (__device__ globals; allocation-free rule)
// ---------------------------------------------------------------------------
__device__ __align__(16) __half g_xnh[NM*NE];          // LN out, fp16
__device__ __align__(16) __half g_qh[NM*NHD];          // q (pre-scaled)
__device__ __align__(16) __half g_kh[NM*NHD];
__device__ __align__(16) __half g_vh[NM*NHD];
__device__ __align__(16) __half g_aoh[NM*NHD];         // attention out
// weights TRANSPOSED: [N][K] K-major; [0..2] = q,k,v (contiguous), [3] = o
__device__ __align__(16) __half g_wh[4][NE*NHD];

// q pre-scale: (1/sqrt(64)) * log2(e)  — softmax runs in exp2 domain
#define QSCALE 0.1803368801111204f

// ---------------------------------------------------------------------------
// PTX helpers
// ---------------------------------------------------------------------------
__device__ __forceinline__ void ldsm4(unsigned r[4], unsigned addr) {
    asm volatile("ldmatrix.sync.aligned.m8n8.x4.shared.b16 {%0,%1,%2,%3}, [%4];"
                 : "=r"(r[0]), "=r"(r[1]), "=r"(r[2]), "=r"(r[3]) : "r"(addr));
}
__device__ __forceinline__ void ldsm4t(unsigned r[4], unsigned addr) {
    asm volatile("ldmatrix.sync.aligned.m8n8.x4.trans.shared.b16 {%0,%1,%2,%3}, [%4];"
                 : "=r"(r[0]), "=r"(r[1]), "=r"(r[2]), "=r"(r[3]) : "r"(addr));
}
__device__ __forceinline__ void mmaf16(float d[4], const unsigned a[4],
                                       unsigned b0, unsigned b1) {
    asm volatile("mma.sync.aligned.m16n8k16.row.col.f32.f16.f16.f32 "
                 "{%0,%1,%2,%3}, {%4,%5,%6,%7}, {%8,%9}, {%0,%1,%2,%3};"
                 : "+f"(d[0]), "+f"(d[1]), "+f"(d[2]), "+f"(d[3])
                 : "r"(a[0]), "r"(a[1]), "r"(a[2]), "r"(a[3]), "r"(b0), "r"(b1));
}
__device__ __forceinline__ void cpa16(unsigned saddr, const void* g) {
    asm volatile("cp.async.cg.shared.global [%0], [%1], 16;" :: "r"(saddr), "l"(g));
}
__device__ __forceinline__ void cpa_commit() {
    asm volatile("cp.async.commit_group;");
}
__device__ __forceinline__ unsigned packh2(float a, float b) {
    __half2 t = __floats2half2_rn(a, b);
    return *(unsigned*)&t;
}
__device__ __forceinline__ float ex2(float x) {
    float y;
    asm("ex2.approx.f32 %0, %1;" : "=f"(y) : "f"(x));
    return y;
}
__device__ __forceinline__ unsigned ex2h2(unsigned x) {
    unsigned y;
    asm("ex2.approx.f16x2 %0, %1;" : "=r"(y) : "r"(x));
    return y;
}
__device__ __forceinline__ unsigned hadd2u(unsigned a, unsigned b) {
    __half2 r = __hadd2(*(__half2*)&a, *(__half2*)&b);
    return *(unsigned*)&r;
}
__device__ __forceinline__ unsigned hmax2u(unsigned a, unsigned b) {
    __half2 r = __hmax2(*(__half2*)&a, *(__half2*)&b);
    return *(unsigned*)&r;
}

// ---------------------------------------------------------------------------
// Fused prep kernel: blocks [0, NM) do LayerNorm rows; blocks [NM, NM+4096)
// do weight transpose+convert (1024 blocks per weight). 256 threads each.
// ---------------------------------------------------------------------------
__global__ void __launch_bounds__(256) prep_kernel(
    const float* __restrict__ x,
    const float* __restrict__ gam, const float* __restrict__ bet,
    const float* __restrict__ w0, const float* __restrict__ w1,
    const float* __restrict__ w2, const float* __restrict__ w3) {
    __shared__ float shm[32][33];
    int bid = blockIdx.x;
    int t = threadIdx.x;

    if (bid < NM) {
        // ---- LayerNorm row ----
        int row = bid;
        const float4* xr = (const float4*)(x + (size_t)row * NE);
        float4 xv = xr[t];
        float s  = xv.x + xv.y + xv.z + xv.w;
        float ss = xv.x*xv.x + xv.y*xv.y + xv.z*xv.z + xv.w*xv.w;
        #pragma unroll
        for (int m = 16; m; m >>= 1) {
            s  += __shfl_xor_sync(0xffffffffu, s,  m);
            ss += __shfl_xor_sync(0xffffffffu, ss, m);
        }
        float* sh1 = &shm[0][0];
        float* sh2 = &shm[1][0];
        if ((t & 31) == 0) { sh1[t >> 5] = s; sh2[t >> 5] = ss; }
        __syncthreads();
        s = 0.f; ss = 0.f;
        #pragma unroll
        for (int w = 0; w < 8; w++) { s += sh1[w]; ss += sh2[w]; }
        float mean = s * (1.f / NE);
        float var  = ss * (1.f / NE) - mean * mean;
        float rstd = rsqrtf(var + 1e-5f);
        float4 gv = ((const float4*)gam)[t];
        float4 bv = ((const float4*)bet)[t];
        __half2 o0 = __floats2half2_rn((xv.x - mean) * rstd * gv.x + bv.x,
                                       (xv.y - mean) * rstd * gv.y + bv.y);
        __half2 o1 = __floats2half2_rn((xv.z - mean) * rstd * gv.z + bv.z,
                                       (xv.w - mean) * rstd * gv.w + bv.w);
        __half2* dst = (__half2*)(g_xnh + (size_t)row * NE + t * 4);
        dst[0] = o0; dst[1] = o1;
    } else {
        // ---- weight transpose tile ----
        int wb = bid - NM;                 // 0..4095
        int w = wb >> 10;                  // weight index
        int tile32 = wb & 1023;            // 0..1023
        const float* src = (w == 0) ? w0 : (w == 1) ? w1 : (w == 2) ? w2 : w3;
        int kb = (tile32 & 31) * 32, nb = (tile32 >> 5) * 32;
        int tx = t & 31, ty = t >> 5;
        #pragma unroll
        for (int i = 0; i < 32; i += 8)
            shm[ty + i][tx] = src[(size_t)(kb + ty + i) * NHD + nb + tx];
        __syncthreads();
        __half* dh = g_wh[w];
        #pragma unroll
        for (int i = 0; i < 32; i += 8) {
            float v = shm[tx][ty + i];       // = W[kb+tx][nb+ty+i]
            int n = nb + ty + i, k = kb + tx;
            dh[(size_t)n * NE + k] = __float2half_rn(v);
        }
    }
}

// ---------------------------------------------------------------------------
// fp16 GEMM: D = A @ B^T. A[M,K] K-major; B[N,K] K-major. Single chain.
// 128x128 tile, BK=64, 8 warps (2x4), 256 thr, cp.async double buffer.
// MODE 0: WO — fp32 C = D + bias0 + resid.
// MODE 1: fused QKV (N=3072) — q *QSCALE; q,k,v fp16 stores.
// ---------------------------------------------------------------------------
template<int MODE>
__global__ void __launch_bounds__(256) gemm_f16(
    const __half* __restrict__ A, const __half* __restrict__ Bh,
    const float* __restrict__ bias0, const float* __restrict__ bias1,
    const float* __restrict__ bias2, const float* __restrict__ resid,
    float* __restrict__ C)
{
    extern __shared__ char smraw[];
    unsigned sa = (unsigned)__cvta_generic_to_shared(smraw);
    int tid = threadIdx.x;
    int bm = blockIdx.y, bn = blockIdx.x;
    int lane = tid & 31, wid = tid >> 5;
    int wm = wid >> 2, wn = wid & 3;

    float acc[4][4][4];
    #pragma unroll
    for (int i = 0; i < 4; i++)
        #pragma unroll
        for (int j = 0; j < 4; j++)
            #pragma unroll
            for (int c = 0; c < 4; c++) acc[i][j][c] = 0.f;

    auto issue = [&](int buf, int k0) {
        unsigned base = sa + buf * 32768;
        #pragma unroll
        for (int i = 0; i < 4; i++) {
            int u = tid + i * 256;
            int row = u >> 3, c = u & 7;
            unsigned so = row * 128 + ((c ^ (row & 7)) << 4);
            cpa16(base + so,         A  + (size_t)(bm * 128 + row) * NE + k0 + c * 8);
            cpa16(base + 16384 + so, Bh + (size_t)(bn * 128 + row) * NE + k0 + c * 8);
        }
        cpa_commit();
    };

    const int iters = NE >> 6;      // K = 1024, BK = 64
    issue(0, 0);

    int r8 = lane & 7, sel = lane >> 3;
    for (int it = 0; it < iters; it++) {
        if (it + 1 < iters) {
            issue((it + 1) & 1, (it + 1) << 6);
            asm volatile("cp.async.wait_group 1;");
        } else {
            asm volatile("cp.async.wait_group 0;");
        }
        __syncthreads();

        unsigned ab  = sa + (it & 1) * 32768;
        unsigned bbh = ab + 16384;
        #pragma unroll
        for (int s = 0; s < 4; s++) {
            int ch = 2 * s + (sel >> 1);
            unsigned aH[4][4], bH[2][4];
            #pragma unroll
            for (int mf = 0; mf < 4; mf++) {
                int row = wm * 64 + mf * 16 + r8 + ((sel & 1) << 3);
                ldsm4(aH[mf], ab + row * 128 + ((ch ^ (row & 7)) << 4));
            }
            #pragma unroll
            for (int np = 0; np < 2; np++) {
                int nrow = wn * 32 + np * 16 + r8 + ((sel & 1) << 3);
                ldsm4(bH[np], bbh + nrow * 128 + ((ch ^ (nrow & 7)) << 4));
            }
            #pragma unroll
            for (int mf = 0; mf < 4; mf++)
                #pragma unroll
                for (int nf = 0; nf < 4; nf++)
                    mmaf16(acc[mf][nf], aH[mf],
                           bH[nf >> 1][nf & 1], bH[nf >> 1][(nf & 1) + 2]);
        }
        __syncthreads();
    }

    int g = lane >> 2, t2 = (lane & 3) * 2;
    if (MODE == 0) {
        #pragma unroll
        for (int mf = 0; mf < 4; mf++) {
            int row0 = bm * 128 + wm * 64 + mf * 16 + g;
            #pragma unroll
            for (int nf = 0; nf < 4; nf++) {
                int col = bn * 128 + wn * 32 + nf * 8 + t2;
                float b0 = bias0[col], b1 = bias0[col + 1];
                const float* rp0 = resid + (size_t)row0 * NHD + col;
                const float* rp1 = resid + (size_t)(row0 + 8) * NHD + col;
                *(float2*)(C + (size_t)row0 * NHD + col) =
                    make_float2(acc[mf][nf][0] + b0 + rp0[0],
                                acc[mf][nf][1] + b1 + rp0[1]);
                *(float2*)(C + (size_t)(row0 + 8) * NHD + col) =
                    make_float2(acc[mf][nf][2] + b0 + rp1[0],
                                acc[mf][nf][3] + b1 + rp1[1]);
            }
        }
    } else {
        int which = bn >> 3;                  // 0:q 1:k 2:v
        const float* bias = (which == 0) ? bias0 : (which == 1) ? bias1 : bias2;
        float scl = (which == 0) ? QSCALE : 1.0f;
        __half* Ch = (which == 0) ? g_qh : (which == 1) ? g_kh : g_vh;
        #pragma unroll
        for (int mf = 0; mf < 4; mf++) {
            int row0 = bm * 128 + wm * 64 + mf * 16 + g;
            #pragma unroll
            for (int nf = 0; nf < 4; nf++) {
                int col = (bn & 7) * 128 + wn * 32 + nf * 8 + t2;
                float v00 = (acc[mf][nf][0] + bias[col])     * scl;
                float v01 = (acc[mf][nf][1] + bias[col + 1]) * scl;
                float v10 = (acc[mf][nf][2] + bias[col])     * scl;
                float v11 = (acc[mf][nf][3] + bias[col + 1]) * scl;
                *(__half2*)(Ch + (size_t)row0 * NHD + col) =
                    __floats2half2_rn(v00, v01);
                *(__half2*)(Ch + (size_t)(row0 + 8) * NHD + col) =
                    __floats2half2_rn(v10, v11);
            }
        }
    }
}

// ---------------------------------------------------------------------------
// Pure-fp16 tensor-core causal flash attention, exp2 f16x2 softmax.
// Block = 4 warps, 64 q-rows, per (b,h). 2-stage KV pipeline.
// Smem: Q 8K | 2 x (K 8K | V 8K) = 40KB.
// __launch_bounds__(128, 5): reg-capped for 5 CTAs/SM (20 warps).
// ph-only P storage (no duplicate arrays); fine-grained diagonal skip.
// ---------------------------------------------------------------------------
__global__ void __launch_bounds__(128, 5) attn_tc_kernel() {
    extern __shared__ char smraw[];
    unsigned sb = (unsigned)__cvta_generic_to_shared(smraw);
    int tid = threadIdx.x, lane = tid & 31, wid = tid >> 5;
    int qt = (int)gridDim.x - 1 - (int)blockIdx.x;   // long blocks first
    int h = blockIdx.y, b = blockIdx.z;
    int g = lane >> 2, t2 = (lane & 3) * 2;
    int r8 = lane & 7, sel = lane >> 3;

    size_t qrow0 = (size_t)(b * NS + qt * 64);

    // Stage Q (own commit group)
    #pragma unroll
    for (int i = 0; i < 4; i++) {
        int u = tid + i * 128;
        int row = u >> 3, c = u & 7;
        size_t go = (qrow0 + row) * NHD + h * ND + c * 8;
        cpa16(sb + row * 128 + ((c ^ (row & 7)) << 4), g_qh + go);
    }
    cpa_commit();

    auto issueKV = [&](int buf, int kt) {
        unsigned base = sb + 8192 + buf * 16384;
        size_t krow0 = (size_t)(b * NS + kt * 64);
        #pragma unroll
        for (int i = 0; i < 4; i++) {
            int u = tid + i * 128;
            int row = u >> 3, c = u & 7;
            size_t go = (krow0 + row) * NHD + h * ND + c * 8;
            unsigned so = row * 128 + ((c ^ (row & 7)) << 4);
            cpa16(base + so,        g_kh + go);
            cpa16(base + 8192 + so, g_vh + go);
        }
        cpa_commit();
    };
    issueKV(0, 0);

    // Wait for Q group (KV0 may stay pending), then load Q fragments
    asm volatile("cp.async.wait_group 1;");
    __syncthreads();
    unsigned aQ[4][4];
    #pragma unroll
    for (int kc = 0; kc < 4; kc++) {
        int row = wid * 16 + r8 + ((sel & 1) << 3);
        int ch = 2 * kc + (sel >> 1);
        ldsm4(aQ[kc], sb + row * 128 + ((ch ^ (row & 7)) << 4));
    }

    float o[8][4];
    #pragma unroll
    for (int d = 0; d < 8; d++)
        #pragma unroll
        for (int c = 0; c < 4; c++) o[d][c] = 0.f;
    float m0 = -60000.f, m1 = -60000.f, l0 = 0.f, l1 = 0.f;

    for (int kt = 0; kt <= qt; kt++) {
        __syncthreads();      // all warps done reading the buffer being refilled
        if (kt < qt) {
            issueKV((kt + 1) & 1, kt + 1);
            asm volatile("cp.async.wait_group 1;");
        } else {
            asm volatile("cp.async.wait_group 0;");
        }
        __syncthreads();
        unsigned kb = sb + 8192 + (kt & 1) * 16384;

        // Diagonal tile: warp wid covers rows [16*wid, 16*wid+15]; only
        // columns <= 16*wid+15 matter -> jf < 2*wid+2, kc < wid+1.
        const bool diag = (kt == qt);
        const int jmax = diag ? (2 * wid + 2) : 8;
        const int kcmax = diag ? (wid + 1) : 4;

        // ---- S = Q K^T (exp2 domain: q pre-scaled by 1/8*log2e) ----
        float s[8][4];
        #pragma unroll
        for (int jf = 0; jf < 8; jf++)
            #pragma unroll
            for (int c = 0; c < 4; c++) s[jf][c] = 0.f;

        #pragma unroll
        for (int kc = 0; kc < 4; kc++) {
            unsigned bh[4][4];
            #pragma unroll
            for (int jp = 0; jp < 4; jp++) {
                if (jp * 2 < jmax) {
                    int jrow = jp * 16 + ((sel >> 1) << 3) + r8;
                    int ch = 2 * kc + (sel & 1);
                    ldsm4(bh[jp], kb + jrow * 128 + ((ch ^ (jrow & 7)) << 4));
                }
            }
            #pragma unroll
            for (int jf = 0; jf < 8; jf++)
                if (jf < jmax)
                    mmaf16(s[jf], aQ[kc],
                           bh[jf >> 1][(jf & 1) * 2], bh[jf >> 1][(jf & 1) * 2 + 1]);
        }

        // ---- causal mask on diagonal tile ----
        if (diag) {
            int rowg = wid * 16 + g;
            #pragma unroll
            for (int jf = 0; jf < 8; jf++) {
                int col = jf * 8 + t2;
                if (col     > rowg)     s[jf][0] = -60000.f;
                if (col + 1 > rowg)     s[jf][1] = -60000.f;
                if (col     > rowg + 8) s[jf][2] = -60000.f;
                if (col + 1 > rowg + 8) s[jf][3] = -60000.f;
            }
        }

        // ---- online softmax: packed-f16 max reduce ----
        float mx0 = -60000.f, mx1 = -60000.f;
        #pragma unroll
        for (int jf = 0; jf < 8; jf++) {
            if (jf < jmax) {
                mx0 = fmaxf(mx0, fmaxf(s[jf][0], s[jf][1]));
                mx1 = fmaxf(mx1, fmaxf(s[jf][2], s[jf][3]));
            }
        }
        unsigned mxp = packh2(mx0, mx1);
        mxp = hmax2u(mxp, __shfl_xor_sync(0xffffffffu, mxp, 1));
        mxp = hmax2u(mxp, __shfl_xor_sync(0xffffffffu, mxp, 2));
        float2 mxf = __half22float2(*(__half2*)&mxp);
        float mn0 = fmaxf(m0, mxf.x), mn1 = fmaxf(m1, mxf.y);
        float a0 = ex2(m0 - mn0), a1 = ex2(m1 - mn1);
        m0 = mn0; m1 = mn1;

        // P fragments: ph[kc][0..3]; [ (jf&1)*2 ] = rows(g) pair, +1 = rows(g+8)
        unsigned ph[4][4];
        #pragma unroll
        for (int jf = 0; jf < 8; jf++) {
            int kc = jf >> 1, hi = (jf & 1) * 2;
            if (jf < jmax) {
                ph[kc][hi]     = ex2h2(packh2(s[jf][0] - mn0, s[jf][1] - mn0));
                ph[kc][hi + 1] = ex2h2(packh2(s[jf][2] - mn1, s[jf][3] - mn1));
            } else {
                ph[kc][hi] = 0u; ph[kc][hi + 1] = 0u;
            }
        }

        // ---- rescale o, then issue PV mmas BEFORE the l reduction ----
        #pragma unroll
        for (int d = 0; d < 8; d++) {
            o[d][0] *= a0; o[d][1] *= a0;
            o[d][2] *= a1; o[d][3] *= a1;
        }
        #pragma unroll
        for (int kc = 0; kc < 4; kc++) {
            if (kc < kcmax) {
                unsigned vh[4][4];
                #pragma unroll
                for (int np = 0; np < 4; np++) {
                    int krow = kc * 16 + (lane & 15);
                    int ch = np * 2 + (lane >> 4);
                    ldsm4t(vh[np], kb + 8192 + krow * 128 + ((ch ^ (krow & 7)) << 4));
                }
                #pragma unroll
                for (int df = 0; df < 8; df++)
                    mmaf16(o[df], ph[kc],
                           vh[df >> 1][(df & 1) * 2], vh[df >> 1][(df & 1) * 2 + 1]);
            }
        }

        // ---- deferred l reduction (reads ph directly; zeros contribute 0) ----
        unsigned s01 = hadd2u(hadd2u(hadd2u(ph[0][0], ph[0][2]),
                                     hadd2u(ph[1][0], ph[1][2])),
                              hadd2u(hadd2u(ph[2][0], ph[2][2]),
                                     hadd2u(ph[3][0], ph[3][2])));
        unsigned s23 = hadd2u(hadd2u(hadd2u(ph[0][1], ph[0][3]),
                                     hadd2u(ph[1][1], ph[1][3])),
                              hadd2u(hadd2u(ph[2][1], ph[2][3]),
                                     hadd2u(ph[3][1], ph[3][3])));
        float2 f01 = __half22float2(*(__half2*)&s01);
        float2 f23 = __half22float2(*(__half2*)&s23);
        float ps0 = f01.x + f01.y;
        float ps1 = f23.x + f23.y;
        ps0 += __shfl_xor_sync(0xffffffffu, ps0, 1);
        ps0 += __shfl_xor_sync(0xffffffffu, ps0, 2);
        ps1 += __shfl_xor_sync(0xffffffffu, ps1, 1);
        ps1 += __shfl_xor_sync(0xffffffffu, ps1, 2);
        l0 = l0 * a0 + ps0;
        l1 = l1 * a1 + ps1;
    }

    // ---- epilogue: normalize, fp16 out ----
    float inv0 = 1.f / l0, inv1 = 1.f / l1;
    size_t row0 = qrow0 + wid * 16 + g;
    #pragma unroll
    for (int df = 0; df < 8; df++) {
        int col = h * ND + df * 8 + t2;
        *(__half2*)(g_aoh + row0 * NHD + col) =
            __floats2half2_rn(o[df][0] * inv0, o[df][1] * inv0);
        *(__half2*)(g_aoh + (row0 + 8) * NHD + col) =
            __floats2half2_rn(o[df][2] * inv1, o[df][3] * inv1);
    }
}

// ---------------------------------------------------------------------------
// Launch
// ---------------------------------------------------------------------------
extern "C" void kernel_launch(void* const* d_in, const int* in_sizes, int n_in,
                              void* d_out, int out_size) {
    const float* x    = (const float*)d_in[0];
    const float* ln_g = (const float*)d_in[1];
    const float* ln_b = (const float*)d_in[2];
    const float* wq   = (const float*)d_in[3];
    const float* bq   = (const float*)d_in[4];
    const float* wk   = (const float*)d_in[5];
    const float* bk   = (const float*)d_in[6];
    const float* wv   = (const float*)d_in[7];
    const float* bv   = (const float*)d_in[8];
    const float* wo   = (const float*)d_in[9];
    const float* bo   = (const float*)d_in[10];
    float* out = (float*)d_out;

    __half *xnh, *aoh, *wh;
    cudaGetSymbolAddress((void**)&xnh, g_xnh);
    cudaGetSymbolAddress((void**)&aoh, g_aoh);
    cudaGetSymbolAddress((void**)&wh,  g_wh);

    prep_kernel<<<NM + 4096, 256>>>(x, ln_g, ln_b, wq, wk, wv, wo);

    cudaFuncSetAttribute(gemm_f16<1>,
                         cudaFuncAttributeMaxDynamicSharedMemorySize, 65536);
    cudaFuncSetAttribute(gemm_f16<0>,
                         cudaFuncAttributeMaxDynamicSharedMemorySize, 65536);

    const size_t WN = (size_t)NE * NHD;
    // fused QKV: B rows 0..3071 span g_wh[0..2]
    gemm_f16<1><<<dim3(3 * NHD / 128, NM / 128), 256, 65536>>>(
        xnh, wh, bq, bk, bv, nullptr, nullptr);

    cudaFuncSetAttribute(attn_tc_kernel,
                         cudaFuncAttributeMaxDynamicSharedMemorySize, 40960);
    attn_tc_kernel<<<dim3(NS / 64, NH, NB), 128, 40960>>>();

    gemm_f16<0><<<dim3(NE / 128, NM / 128), 256, 65536>>>(
        aoh, wh + 3 * WN, bo, nullptr, nullptr, x, out);
}

// round 16
// speedup vs baseline: 1.2397x; 1.2397x over previous
#include <cuda_runtime.h>
#include <cuda_fp16.h>
#include <cstdint>

#define NB 2
#define NS 2048
#define NE 1024
#define NH 16
#define ND 64
#define NM (NB*NS)      // 4096 rows
#define NHD (NH*ND)     // 1024

// ---------------------------------------------------------------------------
// Scratch (__device__ globals; allocation-free rule)
// ---------------------------------------------------------------------------
__device__ __align__(16) __half g_xnh[NM*NE];          // LN out, fp16
__device__ __align__(16) __half g_qh[NM*NHD];          // q (pre-scaled)
__device__ __align__(16) __half g_kh[NM*NHD];
__device__ __align__(16) __half g_vh[NM*NHD];
__device__ __align__(16) __half g_aoh[NM*NHD];         // attention out
// weights TRANSPOSED: [N][K] K-major; [0..2] = q,k,v (contiguous), [3] = o
__device__ __align__(16) __half g_wh[4][NE*NHD];

// q pre-scale: (1/sqrt(64)) * log2(e)  — softmax runs in exp2 domain
#define QSCALE 0.1803368801111204f

// ---------------------------------------------------------------------------
// PTX helpers
// ---------------------------------------------------------------------------
__device__ __forceinline__ void ldsm4(unsigned r[4], unsigned addr) {
    asm volatile("ldmatrix.sync.aligned.m8n8.x4.shared.b16 {%0,%1,%2,%3}, [%4];"
                 : "=r"(r[0]), "=r"(r[1]), "=r"(r[2]), "=r"(r[3]) : "r"(addr));
}
__device__ __forceinline__ void ldsm4t(unsigned r[4], unsigned addr) {
    asm volatile("ldmatrix.sync.aligned.m8n8.x4.trans.shared.b16 {%0,%1,%2,%3}, [%4];"
                 : "=r"(r[0]), "=r"(r[1]), "=r"(r[2]), "=r"(r[3]) : "r"(addr));
}
__device__ __forceinline__ void mmaf16(float d[4], const unsigned a[4],
                                       unsigned b0, unsigned b1) {
    asm volatile("mma.sync.aligned.m16n8k16.row.col.f32.f16.f16.f32 "
                 "{%0,%1,%2,%3}, {%4,%5,%6,%7}, {%8,%9}, {%0,%1,%2,%3};"
                 : "+f"(d[0]), "+f"(d[1]), "+f"(d[2]), "+f"(d[3])
                 : "r"(a[0]), "r"(a[1]), "r"(a[2]), "r"(a[3]), "r"(b0), "r"(b1));
}
__device__ __forceinline__ void cpa16(unsigned saddr, const void* g) {
    asm volatile("cp.async.cg.shared.global [%0], [%1], 16;" :: "r"(saddr), "l"(g));
}
__device__ __forceinline__ void cpa_commit() {
    asm volatile("cp.async.commit_group;");
}
__device__ __forceinline__ unsigned packh2(float a, float b) {
    __half2 t = __floats2half2_rn(a, b);
    return *(unsigned*)&t;
}
__device__ __forceinline__ float ex2(float x) {
    float y;
    asm("ex2.approx.f32 %0, %1;" : "=f"(y) : "f"(x));
    return y;
}
__device__ __forceinline__ unsigned ex2h2(unsigned x) {
    unsigned y;
    asm("ex2.approx.f16x2 %0, %1;" : "=r"(y) : "r"(x));
    return y;
}
__device__ __forceinline__ unsigned hadd2u(unsigned a, unsigned b) {
    __half2 r = __hadd2(*(__half2*)&a, *(__half2*)&b);
    return *(unsigned*)&r;
}
__device__ __forceinline__ unsigned hmax2u(unsigned a, unsigned b) {
    __half2 r = __hmax2(*(__half2*)&a, *(__half2*)&b);
    return *(unsigned*)&r;
}

// ---------------------------------------------------------------------------
// Fused prep kernel: blocks [0, NM) do LayerNorm rows; blocks [NM, NM+4096)
// do weight transpose+convert (1024 blocks per weight). 256 threads each.
// ---------------------------------------------------------------------------
__global__ void __launch_bounds__(256) prep_kernel(
    const float* __restrict__ x,
    const float* __restrict__ gam, const float* __restrict__ bet,
    const float* __restrict__ w0, const float* __restrict__ w1,
    const float* __restrict__ w2, const float* __restrict__ w3) {
    __shared__ float shm[32][33];
    int bid = blockIdx.x;
    int t = threadIdx.x;

    if (bid < NM) {
        // ---- LayerNorm row ----
        int row = bid;
        const float4* xr = (const float4*)(x + (size_t)row * NE);
        float4 xv = xr[t];
        float s  = xv.x + xv.y + xv.z + xv.w;
        float ss = xv.x*xv.x + xv.y*xv.y + xv.z*xv.z + xv.w*xv.w;
        #pragma unroll
        for (int m = 16; m; m >>= 1) {
            s  += __shfl_xor_sync(0xffffffffu, s,  m);
            ss += __shfl_xor_sync(0xffffffffu, ss, m);
        }
        float* sh1 = &shm[0][0];
        float* sh2 = &shm[1][0];
        if ((t & 31) == 0) { sh1[t >> 5] = s; sh2[t >> 5] = ss; }
        __syncthreads();
        s = 0.f; ss = 0.f;
        #pragma unroll
        for (int w = 0; w < 8; w++) { s += sh1[w]; ss += sh2[w]; }
        float mean = s * (1.f / NE);
        float var  = ss * (1.f / NE) - mean * mean;
        float rstd = rsqrtf(var + 1e-5f);
        float4 gv = ((const float4*)gam)[t];
        float4 bv = ((const float4*)bet)[t];
        __half2 o0 = __floats2half2_rn((xv.x - mean) * rstd * gv.x + bv.x,
                                       (xv.y - mean) * rstd * gv.y + bv.y);
        __half2 o1 = __floats2half2_rn((xv.z - mean) * rstd * gv.z + bv.z,
                                       (xv.w - mean) * rstd * gv.w + bv.w);
        __half2* dst = (__half2*)(g_xnh + (size_t)row * NE + t * 4);
        dst[0] = o0; dst[1] = o1;
    } else {
        // ---- weight transpose tile ----
        int wb = bid - NM;                 // 0..4095
        int w = wb >> 10;                  // weight index
        int tile32 = wb & 1023;            // 0..1023
        const float* src = (w == 0) ? w0 : (w == 1) ? w1 : (w == 2) ? w2 : w3;
        int kb = (tile32 & 31) * 32, nb = (tile32 >> 5) * 32;
        int tx = t & 31, ty = t >> 5;
        #pragma unroll
        for (int i = 0; i < 32; i += 8)
            shm[ty + i][tx] = src[(size_t)(kb + ty + i) * NHD + nb + tx];
        __syncthreads();
        __half* dh = g_wh[w];
        #pragma unroll
        for (int i = 0; i < 32; i += 8) {
            float v = shm[tx][ty + i];       // = W[kb+tx][nb+ty+i]
            int n = nb + ty + i, k = kb + tx;
            dh[(size_t)n * NE + k] = __float2half_rn(v);
        }
    }
}

// ---------------------------------------------------------------------------
// fp16 GEMM: D = A @ B^T. A[M,K] K-major; B[N,K] K-major. Single chain.
// 128x128 tile, BK=64, 8 warps (2x4), 256 thr, cp.async double buffer.
// MODE 0: WO — fp32 C = D + bias0 + resid.
// MODE 1: fused QKV (N=3072) — q *QSCALE; q,k,v fp16 stores.
// ---------------------------------------------------------------------------
template<int MODE>
__global__ void __launch_bounds__(256) gemm_f16(
    const __half* __restrict__ A, const __half* __restrict__ Bh,
    const float* __restrict__ bias0, const float* __restrict__ bias1,
    const float* __restrict__ bias2, const float* __restrict__ resid,
    float* __restrict__ C)
{
    extern __shared__ char smraw[];
    unsigned sa = (unsigned)__cvta_generic_to_shared(smraw);
    int tid = threadIdx.x;
    int bm = blockIdx.y, bn = blockIdx.x;
    int lane = tid & 31, wid = tid >> 5;
    int wm = wid >> 2, wn = wid & 3;

    float acc[4][4][4];
    #pragma unroll
    for (int i = 0; i < 4; i++)
        #pragma unroll
        for (int j = 0; j < 4; j++)
            #pragma unroll
            for (int c = 0; c < 4; c++) acc[i][j][c] = 0.f;

    auto issue = [&](int buf, int k0) {
        unsigned base = sa + buf * 32768;
        #pragma unroll
        for (int i = 0; i < 4; i++) {
            int u = tid + i * 256;
            int row = u >> 3, c = u & 7;
            unsigned so = row * 128 + ((c ^ (row & 7)) << 4);
            cpa16(base + so,         A  + (size_t)(bm * 128 + row) * NE + k0 + c * 8);
            cpa16(base + 16384 + so, Bh + (size_t)(bn * 128 + row) * NE + k0 + c * 8);
        }
        cpa_commit();
    };

    const int iters = NE >> 6;      // K = 1024, BK = 64
    issue(0, 0);

    int r8 = lane & 7, sel = lane >> 3;
    for (int it = 0; it < iters; it++) {
        if (it + 1 < iters) {
            issue((it + 1) & 1, (it + 1) << 6);
            asm volatile("cp.async.wait_group 1;");
        } else {
            asm volatile("cp.async.wait_group 0;");
        }
        __syncthreads();

        unsigned ab  = sa + (it & 1) * 32768;
        unsigned bbh = ab + 16384;
        #pragma unroll
        for (int s = 0; s < 4; s++) {
            int ch = 2 * s + (sel >> 1);
            unsigned aH[4][4], bH[2][4];
            #pragma unroll
            for (int mf = 0; mf < 4; mf++) {
                int row = wm * 64 + mf * 16 + r8 + ((sel & 1) << 3);
                ldsm4(aH[mf], ab + row * 128 + ((ch ^ (row & 7)) << 4));
            }
            #pragma unroll
            for (int np = 0; np < 2; np++) {
                int nrow = wn * 32 + np * 16 + r8 + ((sel & 1) << 3);
                ldsm4(bH[np], bbh + nrow * 128 + ((ch ^ (nrow & 7)) << 4));
            }
            #pragma unroll
            for (int mf = 0; mf < 4; mf++)
                #pragma unroll
                for (int nf = 0; nf < 4; nf++)
                    mmaf16(acc[mf][nf], aH[mf],
                           bH[nf >> 1][nf & 1], bH[nf >> 1][(nf & 1) + 2]);
        }
        __syncthreads();
    }

    int g = lane >> 2, t2 = (lane & 3) * 2;
    if (MODE == 0) {
        #pragma unroll
        for (int mf = 0; mf < 4; mf++) {
            int row0 = bm * 128 + wm * 64 + mf * 16 + g;
            #pragma unroll
            for (int nf = 0; nf < 4; nf++) {
                int col = bn * 128 + wn * 32 + nf * 8 + t2;
                float b0 = bias0[col], b1 = bias0[col + 1];
                const float* rp0 = resid + (size_t)row0 * NHD + col;
                const float* rp1 = resid + (size_t)(row0 + 8) * NHD + col;
                *(float2*)(C + (size_t)row0 * NHD + col) =
                    make_float2(acc[mf][nf][0] + b0 + rp0[0],
                                acc[mf][nf][1] + b1 + rp0[1]);
                *(float2*)(C + (size_t)(row0 + 8) * NHD + col) =
                    make_float2(acc[mf][nf][2] + b0 + rp1[0],
                                acc[mf][nf][3] + b1 + rp1[1]);
            }
        }
    } else {
        int which = bn >> 3;                  // 0:q 1:k 2:v
        const float* bias = (which == 0) ? bias0 : (which == 1) ? bias1 : bias2;
        float scl = (which == 0) ? QSCALE : 1.0f;
        __half* Ch = (which == 0) ? g_qh : (which == 1) ? g_kh : g_vh;
        #pragma unroll
        for (int mf = 0; mf < 4; mf++) {
            int row0 = bm * 128 + wm * 64 + mf * 16 + g;
            #pragma unroll
            for (int nf = 0; nf < 4; nf++) {
                int col = (bn & 7) * 128 + wn * 32 + nf * 8 + t2;
                float v00 = (acc[mf][nf][0] + bias[col])     * scl;
                float v01 = (acc[mf][nf][1] + bias[col + 1]) * scl;
                float v10 = (acc[mf][nf][2] + bias[col])     * scl;
                float v11 = (acc[mf][nf][3] + bias[col + 1]) * scl;
                *(__half2*)(Ch + (size_t)row0 * NHD + col) =
                    __floats2half2_rn(v00, v01);
                *(__half2*)(Ch + (size_t)(row0 + 8) * NHD + col) =
                    __floats2half2_rn(v10, v11);
            }
        }
    }
}

// ---------------------------------------------------------------------------
// Pure-fp16 tensor-core causal flash attention, exp2 f16x2 softmax.
// Block = 4 warps, 64 q-rows, per (b,h). 2-stage KV pipeline.
// Smem: Q 8K | 2 x (K 8K | V 8K) = 40KB. (R12 structure, natural regs.)
// Warp-uniform diagonal skip: on kt==qt warp wid only computes jf<2*wid+2,
// kc<wid+1 (the rest is fully masked); skipped P fragments zeroed for l-sum.
// ---------------------------------------------------------------------------
__global__ void __launch_bounds__(128) attn_tc_kernel() {
    extern __shared__ char smraw[];
    unsigned sb = (unsigned)__cvta_generic_to_shared(smraw);
    int tid = threadIdx.x, lane = tid & 31, wid = tid >> 5;
    int qt = (int)gridDim.x - 1 - (int)blockIdx.x;   // long blocks first
    int h = blockIdx.y, b = blockIdx.z;
    int g = lane >> 2, t2 = (lane & 3) * 2;
    int r8 = lane & 7, sel = lane >> 3;

    size_t qrow0 = (size_t)(b * NS + qt * 64);

    // Stage Q (own commit group)
    #pragma unroll
    for (int i = 0; i < 4; i++) {
        int u = tid + i * 128;
        int row = u >> 3, c = u & 7;
        size_t go = (qrow0 + row) * NHD + h * ND + c * 8;
        cpa16(sb + row * 128 + ((c ^ (row & 7)) << 4), g_qh + go);
    }
    cpa_commit();

    auto issueKV = [&](int buf, int kt) {
        unsigned base = sb + 8192 + buf * 16384;
        size_t krow0 = (size_t)(b * NS + kt * 64);
        #pragma unroll
        for (int i = 0; i < 4; i++) {
            int u = tid + i * 128;
            int row = u >> 3, c = u & 7;
            size_t go = (krow0 + row) * NHD + h * ND + c * 8;
            unsigned so = row * 128 + ((c ^ (row & 7)) << 4);
            cpa16(base + so,        g_kh + go);
            cpa16(base + 8192 + so, g_vh + go);
        }
        cpa_commit();
    };
    issueKV(0, 0);

    // Wait for Q group (KV0 may stay pending), then load Q fragments
    asm volatile("cp.async.wait_group 1;");
    __syncthreads();
    unsigned aQ[4][4];
    #pragma unroll
    for (int kc = 0; kc < 4; kc++) {
        int row = wid * 16 + r8 + ((sel & 1) << 3);
        int ch = 2 * kc + (sel >> 1);
        ldsm4(aQ[kc], sb + row * 128 + ((ch ^ (row & 7)) << 4));
    }

    float o[8][4];
    #pragma unroll
    for (int d = 0; d < 8; d++)
        #pragma unroll
        for (int c = 0; c < 4; c++) o[d][c] = 0.f;
    float m0 = -60000.f, m1 = -60000.f, l0 = 0.f, l1 = 0.f;

    for (int kt = 0; kt <= qt; kt++) {
        __syncthreads();      // all warps done reading the buffer being refilled
        if (kt < qt) {
            issueKV((kt + 1) & 1, kt + 1);
            asm volatile("cp.async.wait_group 1;");
        } else {
            asm volatile("cp.async.wait_group 0;");
        }
        __syncthreads();
        unsigned kb = sb + 8192 + (kt & 1) * 16384;

        // Diagonal tile: warp wid rows [16w,16w+15]; cols>16w+15 fully masked.
        const bool diag = (kt == qt);
        const int jmax  = diag ? (2 * wid + 2) : 8;
        const int kcmax = diag ? (wid + 1) : 4;

        // ---- S = Q K^T (exp2 domain: q pre-scaled by 1/8*log2e) ----
        float s[8][4];
        #pragma unroll
        for (int jf = 0; jf < 8; jf++)
            #pragma unroll
            for (int c = 0; c < 4; c++) s[jf][c] = 0.f;

        #pragma unroll
        for (int kc = 0; kc < 4; kc++) {
            unsigned bh[4][4];
            #pragma unroll
            for (int jp = 0; jp < 4; jp++) {
                if (jp * 2 < jmax) {
                    int jrow = jp * 16 + ((sel >> 1) << 3) + r8;
                    int ch = 2 * kc + (sel & 1);
                    ldsm4(bh[jp], kb + jrow * 128 + ((ch ^ (jrow & 7)) << 4));
                }
            }
            #pragma unroll
            for (int jf = 0; jf < 8; jf++)
                if (jf < jmax)
                    mmaf16(s[jf], aQ[kc],
                           bh[jf >> 1][(jf & 1) * 2], bh[jf >> 1][(jf & 1) * 2 + 1]);
        }

        // ---- causal mask on diagonal tile ----
        if (diag) {
            int rowg = wid * 16 + g;
            #pragma unroll
            for (int jf = 0; jf < 8; jf++) {
                int col = jf * 8 + t2;
                if (col     > rowg)     s[jf][0] = -60000.f;
                if (col + 1 > rowg)     s[jf][1] = -60000.f;
                if (col     > rowg + 8) s[jf][2] = -60000.f;
                if (col + 1 > rowg + 8) s[jf][3] = -60000.f;
            }
        }

        // ---- online softmax: packed-f16 max reduce ----
        float mx0 = -60000.f, mx1 = -60000.f;
        #pragma unroll
        for (int jf = 0; jf < 8; jf++) {
            if (jf < jmax) {
                mx0 = fmaxf(mx0, fmaxf(s[jf][0], s[jf][1]));
                mx1 = fmaxf(mx1, fmaxf(s[jf][2], s[jf][3]));
            }
        }
        unsigned mxp = packh2(mx0, mx1);
        mxp = hmax2u(mxp, __shfl_xor_sync(0xffffffffu, mxp, 1));
        mxp = hmax2u(mxp, __shfl_xor_sync(0xffffffffu, mxp, 2));
        float2 mxf = __half22float2(*(__half2*)&mxp);
        float mn0 = fmaxf(m0, mxf.x), mn1 = fmaxf(m1, mxf.y);
        float a0 = ex2(m0 - mn0), a1 = ex2(m1 - mn1);
        m0 = mn0; m1 = mn1;

        unsigned ph[4][4];
        unsigned P01[8], P23[8];
        #pragma unroll
        for (int jf = 0; jf < 8; jf++) {
            int kc = jf >> 1, hi = (jf & 1) * 2;
            if (jf < jmax) {
                P01[jf] = ex2h2(packh2(s[jf][0] - mn0, s[jf][1] - mn0));
                P23[jf] = ex2h2(packh2(s[jf][2] - mn1, s[jf][3] - mn1));
            } else {
                P01[jf] = 0u;
                P23[jf] = 0u;
            }
            ph[kc][hi]     = P01[jf];
            ph[kc][hi + 1] = P23[jf];
        }

        // ---- rescale o, then issue PV mmas BEFORE the l reduction ----
        #pragma unroll
        for (int d = 0; d < 8; d++) {
            o[d][0] *= a0; o[d][1] *= a0;
            o[d][2] *= a1; o[d][3] *= a1;
        }
        #pragma unroll
        for (int kc = 0; kc < 4; kc++) {
            if (kc < kcmax) {
                unsigned vh[4][4];
                #pragma unroll
                for (int np = 0; np < 4; np++) {
                    int krow = kc * 16 + (lane & 15);
                    int ch = np * 2 + (lane >> 4);
                    ldsm4t(vh[np], kb + 8192 + krow * 128 + ((ch ^ (krow & 7)) << 4));
                }
                #pragma unroll
                for (int df = 0; df < 8; df++)
                    mmaf16(o[df], ph[kc],
                           vh[df >> 1][(df & 1) * 2], vh[df >> 1][(df & 1) * 2 + 1]);
            }
        }

        // ---- deferred l reduction (hidden behind PV mma issue) ----
        unsigned s01 = hadd2u(hadd2u(hadd2u(P01[0], P01[1]), hadd2u(P01[2], P01[3])),
                              hadd2u(hadd2u(P01[4], P01[5]), hadd2u(P01[6], P01[7])));
        unsigned s23 = hadd2u(hadd2u(hadd2u(P23[0], P23[1]), hadd2u(P23[2], P23[3])),
                              hadd2u(hadd2u(P23[4], P23[5]), hadd2u(P23[6], P23[7])));
        float2 f01 = __half22float2(*(__half2*)&s01);
        float2 f23 = __half22float2(*(__half2*)&s23);
        float ps0 = f01.x + f01.y;
        float ps1 = f23.x + f23.y;
        ps0 += __shfl_xor_sync(0xffffffffu, ps0, 1);
        ps0 += __shfl_xor_sync(0xffffffffu, ps0, 2);
        ps1 += __shfl_xor_sync(0xffffffffu, ps1, 1);
        ps1 += __shfl_xor_sync(0xffffffffu, ps1, 2);
        l0 = l0 * a0 + ps0;
        l1 = l1 * a1 + ps1;
    }

    // ---- epilogue: normalize, fp16 out ----
    float inv0 = 1.f / l0, inv1 = 1.f / l1;
    size_t row0 = qrow0 + wid * 16 + g;
    #pragma unroll
    for (int df = 0; df < 8; df++) {
        int col = h * ND + df * 8 + t2;
        *(__half2*)(g_aoh + row0 * NHD + col) =
            __floats2half2_rn(o[df][0] * inv0, o[df][1] * inv0);
        *(__half2*)(g_aoh + (row0 + 8) * NHD + col) =
            __floats2half2_rn(o[df][2] * inv1, o[df][3] * inv1);
    }
}

// ---------------------------------------------------------------------------
// Launch
// ---------------------------------------------------------------------------
extern "C" void kernel_launch(void* const* d_in, const int* in_sizes, int n_in,
                              void* d_out, int out_size) {
    const float* x    = (const float*)d_in[0];
    const float* ln_g = (const float*)d_in[1];
    const float* ln_b = (const float*)d_in[2];
    const float* wq   = (const float*)d_in[3];
    const float* bq   = (const float*)d_in[4];
    const float* wk   = (const float*)d_in[5];
    const float* bk   = (const float*)d_in[6];
    const float* wv   = (const float*)d_in[7];
    const float* bv   = (const float*)d_in[8];
    const float* wo   = (const float*)d_in[9];
    const float* bo   = (const float*)d_in[10];
    float* out = (float*)d_out;

    __half *xnh, *aoh, *wh;
    cudaGetSymbolAddress((void**)&xnh, g_xnh);
    cudaGetSymbolAddress((void**)&aoh, g_aoh);
    cudaGetSymbolAddress((void**)&wh,  g_wh);

    prep_kernel<<<NM + 4096, 256>>>(x, ln_g, ln_b, wq, wk, wv, wo);

    cudaFuncSetAttribute(gemm_f16<1>,
                         cudaFuncAttributeMaxDynamicSharedMemorySize, 65536);
    cudaFuncSetAttribute(gemm_f16<0>,
                         cudaFuncAttributeMaxDynamicSharedMemorySize, 65536);

    const size_t WN = (size_t)NE * NHD;
    // fused QKV: B rows 0..3071 span g_wh[0..2]
    gemm_f16<1><<<dim3(3 * NHD / 128, NM / 128), 256, 65536>>>(
        xnh, wh, bq, bk, bv, nullptr, nullptr);

    cudaFuncSetAttribute(attn_tc_kernel,
                         cudaFuncAttributeMaxDynamicSharedMemorySize, 40960);
    attn_tc_kernel<<<dim3(NS / 64, NH, NB), 128, 40960>>>();

    gemm_f16<0><<<dim3(NE / 128, NM / 128), 256, 65536>>>(
        aoh, wh + 3 * WN, bo, nullptr, nullptr, x, out);
}

// round 17
// speedup vs baseline: 1.3179x; 1.0631x over previous
#include <cuda_runtime.h>
#include <cuda_fp16.h>
#include <cstdint>

#define NB 2
#define NS 2048
#define NE 1024
#define NH 16
#define ND 64
#define NM (NB*NS)      // 4096 rows
#define NHD (NH*ND)     // 1024

// ---------------------------------------------------------------------------
// Scratch (__device__ globals; allocation-free rule)
// ---------------------------------------------------------------------------
__device__ __align__(16) __half g_xnh[NM*NE];          // LN out, fp16
__device__ __align__(16) __half g_qh[NM*NHD];          // q (pre-scaled)
__device__ __align__(16) __half g_kh[NM*NHD];
__device__ __align__(16) __half g_vh[NM*NHD];
__device__ __align__(16) __half g_aoh[NM*NHD];         // attention out
// weights TRANSPOSED: [N][K] K-major; [0..2] = q,k,v (contiguous), [3] = o
__device__ __align__(16) __half g_wh[4][NE*NHD];

// q pre-scale: (1/sqrt(64)) * log2(e)  — softmax runs in exp2 domain
#define QSCALE 0.1803368801111204f

// ---------------------------------------------------------------------------
// PTX helpers
// ---------------------------------------------------------------------------
__device__ __forceinline__ void ldsm4(unsigned r[4], unsigned addr) {
    asm volatile("ldmatrix.sync.aligned.m8n8.x4.shared.b16 {%0,%1,%2,%3}, [%4];"
                 : "=r"(r[0]), "=r"(r[1]), "=r"(r[2]), "=r"(r[3]) : "r"(addr));
}
__device__ __forceinline__ void ldsm4t(unsigned r[4], unsigned addr) {
    asm volatile("ldmatrix.sync.aligned.m8n8.x4.trans.shared.b16 {%0,%1,%2,%3}, [%4];"
                 : "=r"(r[0]), "=r"(r[1]), "=r"(r[2]), "=r"(r[3]) : "r"(addr));
}
__device__ __forceinline__ void mmaf16(float d[4], const unsigned a[4],
                                       unsigned b0, unsigned b1) {
    asm volatile("mma.sync.aligned.m16n8k16.row.col.f32.f16.f16.f32 "
                 "{%0,%1,%2,%3}, {%4,%5,%6,%7}, {%8,%9}, {%0,%1,%2,%3};"
                 : "+f"(d[0]), "+f"(d[1]), "+f"(d[2]), "+f"(d[3])
                 : "r"(a[0]), "r"(a[1]), "r"(a[2]), "r"(a[3]), "r"(b0), "r"(b1));
}
__device__ __forceinline__ void cpa16(unsigned saddr, const void* g) {
    asm volatile("cp.async.cg.shared.global [%0], [%1], 16;" :: "r"(saddr), "l"(g));
}
__device__ __forceinline__ void cpa_commit() {
    asm volatile("cp.async.commit_group;");
}
__device__ __forceinline__ unsigned packh2(float a, float b) {
    __half2 t = __floats2half2_rn(a, b);
    return *(unsigned*)&t;
}
__device__ __forceinline__ float ex2(float x) {
    float y;
    asm("ex2.approx.f32 %0, %1;" : "=f"(y) : "f"(x));
    return y;
}
__device__ __forceinline__ unsigned ex2h2(unsigned x) {
    unsigned y;
    asm("ex2.approx.f16x2 %0, %1;" : "=r"(y) : "r"(x));
    return y;
}
__device__ __forceinline__ unsigned hadd2u(unsigned a, unsigned b) {
    __half2 r = __hadd2(*(__half2*)&a, *(__half2*)&b);
    return *(unsigned*)&r;
}
__device__ __forceinline__ unsigned hmax2u(unsigned a, unsigned b) {
    __half2 r = __hmax2(*(__half2*)&a, *(__half2*)&b);
    return *(unsigned*)&r;
}

// ---------------------------------------------------------------------------
// Fused prep kernel: blocks [0, NM) do LayerNorm rows; blocks [NM, NM+4096)
// do weight transpose+convert (1024 blocks per weight). 256 threads each.
// ---------------------------------------------------------------------------
__global__ void __launch_bounds__(256) prep_kernel(
    const float* __restrict__ x,
    const float* __restrict__ gam, const float* __restrict__ bet,
    const float* __restrict__ w0, const float* __restrict__ w1,
    const float* __restrict__ w2, const float* __restrict__ w3) {
    __shared__ float shm[32][33];
    int bid = blockIdx.x;
    int t = threadIdx.x;

    if (bid < NM) {
        // ---- LayerNorm row ----
        int row = bid;
        const float4* xr = (const float4*)(x + (size_t)row * NE);
        float4 xv = xr[t];
        float s  = xv.x + xv.y + xv.z + xv.w;
        float ss = xv.x*xv.x + xv.y*xv.y + xv.z*xv.z + xv.w*xv.w;
        #pragma unroll
        for (int m = 16; m; m >>= 1) {
            s  += __shfl_xor_sync(0xffffffffu, s,  m);
            ss += __shfl_xor_sync(0xffffffffu, ss, m);
        }
        float* sh1 = &shm[0][0];
        float* sh2 = &shm[1][0];
        if ((t & 31) == 0) { sh1[t >> 5] = s; sh2[t >> 5] = ss; }
        __syncthreads();
        s = 0.f; ss = 0.f;
        #pragma unroll
        for (int w = 0; w < 8; w++) { s += sh1[w]; ss += sh2[w]; }
        float mean = s * (1.f / NE);
        float var  = ss * (1.f / NE) - mean * mean;
        float rstd = rsqrtf(var + 1e-5f);
        float4 gv = ((const float4*)gam)[t];
        float4 bv = ((const float4*)bet)[t];
        __half2 o0 = __floats2half2_rn((xv.x - mean) * rstd * gv.x + bv.x,
                                       (xv.y - mean) * rstd * gv.y + bv.y);
        __half2 o1 = __floats2half2_rn((xv.z - mean) * rstd * gv.z + bv.z,
                                       (xv.w - mean) * rstd * gv.w + bv.w);
        __half2* dst = (__half2*)(g_xnh + (size_t)row * NE + t * 4);
        dst[0] = o0; dst[1] = o1;
    } else {
        // ---- weight transpose tile ----
        int wb = bid - NM;                 // 0..4095
        int w = wb >> 10;                  // weight index
        int tile32 = wb & 1023;            // 0..1023
        const float* src = (w == 0) ? w0 : (w == 1) ? w1 : (w == 2) ? w2 : w3;
        int kb = (tile32 & 31) * 32, nb = (tile32 >> 5) * 32;
        int tx = t & 31, ty = t >> 5;
        #pragma unroll
        for (int i = 0; i < 32; i += 8)
            shm[ty + i][tx] = src[(size_t)(kb + ty + i) * NHD + nb + tx];
        __syncthreads();
        __half* dh = g_wh[w];
        #pragma unroll
        for (int i = 0; i < 32; i += 8) {
            float v = shm[tx][ty + i];       // = W[kb+tx][nb+ty+i]
            int n = nb + ty + i, k = kb + tx;
            dh[(size_t)n * NE + k] = __float2half_rn(v);
        }
    }
}

// ---------------------------------------------------------------------------
// fp16 GEMM: D = A @ B^T. A[M,K] K-major; B[N,K] K-major. Single chain.
// 128x128 tile, BK=64, 8 warps (2x4), 256 thr, cp.async double buffer.
// MODE 0: WO — fp32 C = D + bias0 + resid.
// MODE 1: fused QKV (N=3072) — q *QSCALE; q,k,v fp16 stores.
// ---------------------------------------------------------------------------
template<int MODE>
__global__ void __launch_bounds__(256) gemm_f16(
    const __half* __restrict__ A, const __half* __restrict__ Bh,
    const float* __restrict__ bias0, const float* __restrict__ bias1,
    const float* __restrict__ bias2, const float* __restrict__ resid,
    float* __restrict__ C)
{
    extern __shared__ char smraw[];
    unsigned sa = (unsigned)__cvta_generic_to_shared(smraw);
    int tid = threadIdx.x;
    int bm = blockIdx.y, bn = blockIdx.x;
    int lane = tid & 31, wid = tid >> 5;
    int wm = wid >> 2, wn = wid & 3;

    float acc[4][4][4];
    #pragma unroll
    for (int i = 0; i < 4; i++)
        #pragma unroll
        for (int j = 0; j < 4; j++)
            #pragma unroll
            for (int c = 0; c < 4; c++) acc[i][j][c] = 0.f;

    auto issue = [&](int buf, int k0) {
        unsigned base = sa + buf * 32768;
        #pragma unroll
        for (int i = 0; i < 4; i++) {
            int u = tid + i * 256;
            int row = u >> 3, c = u & 7;
            unsigned so = row * 128 + ((c ^ (row & 7)) << 4);
            cpa16(base + so,         A  + (size_t)(bm * 128 + row) * NE + k0 + c * 8);
            cpa16(base + 16384 + so, Bh + (size_t)(bn * 128 + row) * NE + k0 + c * 8);
        }
        cpa_commit();
    };

    const int iters = NE >> 6;      // K = 1024, BK = 64
    issue(0, 0);

    int r8 = lane & 7, sel = lane >> 3;
    for (int it = 0; it < iters; it++) {
        if (it + 1 < iters) {
            issue((it + 1) & 1, (it + 1) << 6);
            asm volatile("cp.async.wait_group 1;");
        } else {
            asm volatile("cp.async.wait_group 0;");
        }
        __syncthreads();

        unsigned ab  = sa + (it & 1) * 32768;
        unsigned bbh = ab + 16384;
        #pragma unroll
        for (int s = 0; s < 4; s++) {
            int ch = 2 * s + (sel >> 1);
            unsigned aH[4][4], bH[2][4];
            #pragma unroll
            for (int mf = 0; mf < 4; mf++) {
                int row = wm * 64 + mf * 16 + r8 + ((sel & 1) << 3);
                ldsm4(aH[mf], ab + row * 128 + ((ch ^ (row & 7)) << 4));
            }
            #pragma unroll
            for (int np = 0; np < 2; np++) {
                int nrow = wn * 32 + np * 16 + r8 + ((sel & 1) << 3);
                ldsm4(bH[np], bbh + nrow * 128 + ((ch ^ (nrow & 7)) << 4));
            }
            #pragma unroll
            for (int mf = 0; mf < 4; mf++)
                #pragma unroll
                for (int nf = 0; nf < 4; nf++)
                    mmaf16(acc[mf][nf], aH[mf],
                           bH[nf >> 1][nf & 1], bH[nf >> 1][(nf & 1) + 2]);
        }
        __syncthreads();
    }

    int g = lane >> 2, t2 = (lane & 3) * 2;
    if (MODE == 0) {
        #pragma unroll
        for (int mf = 0; mf < 4; mf++) {
            int row0 = bm * 128 + wm * 64 + mf * 16 + g;
            #pragma unroll
            for (int nf = 0; nf < 4; nf++) {
                int col = bn * 128 + wn * 32 + nf * 8 + t2;
                float b0 = bias0[col], b1 = bias0[col + 1];
                const float* rp0 = resid + (size_t)row0 * NHD + col;
                const float* rp1 = resid + (size_t)(row0 + 8) * NHD + col;
                *(float2*)(C + (size_t)row0 * NHD + col) =
                    make_float2(acc[mf][nf][0] + b0 + rp0[0],
                                acc[mf][nf][1] + b1 + rp0[1]);
                *(float2*)(C + (size_t)(row0 + 8) * NHD + col) =
                    make_float2(acc[mf][nf][2] + b0 + rp1[0],
                                acc[mf][nf][3] + b1 + rp1[1]);
            }
        }
    } else {
        int which = bn >> 3;                  // 0:q 1:k 2:v
        const float* bias = (which == 0) ? bias0 : (which == 1) ? bias1 : bias2;
        float scl = (which == 0) ? QSCALE : 1.0f;
        __half* Ch = (which == 0) ? g_qh : (which == 1) ? g_kh : g_vh;
        #pragma unroll
        for (int mf = 0; mf < 4; mf++) {
            int row0 = bm * 128 + wm * 64 + mf * 16 + g;
            #pragma unroll
            for (int nf = 0; nf < 4; nf++) {
                int col = (bn & 7) * 128 + wn * 32 + nf * 8 + t2;
                float v00 = (acc[mf][nf][0] + bias[col])     * scl;
                float v01 = (acc[mf][nf][1] + bias[col + 1]) * scl;
                float v10 = (acc[mf][nf][2] + bias[col])     * scl;
                float v11 = (acc[mf][nf][3] + bias[col + 1]) * scl;
                *(__half2*)(Ch + (size_t)row0 * NHD + col) =
                    __floats2half2_rn(v00, v01);
                *(__half2*)(Ch + (size_t)(row0 + 8) * NHD + col) =
                    __floats2half2_rn(v10, v11);
            }
        }
    }
}

// ---------------------------------------------------------------------------
// Pure-fp16 tensor-core causal flash attention, exp2 f16x2 softmax.
// Block = 4 warps, 64 q-rows, per (b,h). 2-stage KV pipeline.
// Smem: Q 8K | 2 x (K 8K | V 8K) = 40KB.
// l-reduction deferred past PV mma; max reduction packed f16 (1 shfl chain).
// ---------------------------------------------------------------------------
__global__ void __launch_bounds__(128) attn_tc_kernel() {
    extern __shared__ char smraw[];
    unsigned sb = (unsigned)__cvta_generic_to_shared(smraw);
    int tid = threadIdx.x, lane = tid & 31, wid = tid >> 5;
    int qt = (int)gridDim.x - 1 - (int)blockIdx.x;   // long blocks first
    int h = blockIdx.y, b = blockIdx.z;
    int g = lane >> 2, t2 = (lane & 3) * 2;
    int r8 = lane & 7, sel = lane >> 3;

    size_t qrow0 = (size_t)(b * NS + qt * 64);

    // Stage Q (own commit group)
    #pragma unroll
    for (int i = 0; i < 4; i++) {
        int u = tid + i * 128;
        int row = u >> 3, c = u & 7;
        size_t go = (qrow0 + row) * NHD + h * ND + c * 8;
        cpa16(sb + row * 128 + ((c ^ (row & 7)) << 4), g_qh + go);
    }
    cpa_commit();

    auto issueKV = [&](int buf, int kt) {
        unsigned base = sb + 8192 + buf * 16384;
        size_t krow0 = (size_t)(b * NS + kt * 64);
        #pragma unroll
        for (int i = 0; i < 4; i++) {
            int u = tid + i * 128;
            int row = u >> 3, c = u & 7;
            size_t go = (krow0 + row) * NHD + h * ND + c * 8;
            unsigned so = row * 128 + ((c ^ (row & 7)) << 4);
            cpa16(base + so,        g_kh + go);
            cpa16(base + 8192 + so, g_vh + go);
        }
        cpa_commit();
    };
    issueKV(0, 0);

    // Wait for Q group (KV0 may stay pending), then load Q fragments
    asm volatile("cp.async.wait_group 1;");
    __syncthreads();
    unsigned aQ[4][4];
    #pragma unroll
    for (int kc = 0; kc < 4; kc++) {
        int row = wid * 16 + r8 + ((sel & 1) << 3);
        int ch = 2 * kc + (sel >> 1);
        ldsm4(aQ[kc], sb + row * 128 + ((ch ^ (row & 7)) << 4));
    }

    float o[8][4];
    #pragma unroll
    for (int d = 0; d < 8; d++)
        #pragma unroll
        for (int c = 0; c < 4; c++) o[d][c] = 0.f;
    float m0 = -60000.f, m1 = -60000.f, l0 = 0.f, l1 = 0.f;

    for (int kt = 0; kt <= qt; kt++) {
        __syncthreads();      // all warps done reading the buffer being refilled
        if (kt < qt) {
            issueKV((kt + 1) & 1, kt + 1);
            asm volatile("cp.async.wait_group 1;");
        } else {
            asm volatile("cp.async.wait_group 0;");
        }
        __syncthreads();
        unsigned kb = sb + 8192 + (kt & 1) * 16384;

        // ---- S = Q K^T (exp2 domain: q pre-scaled by 1/8*log2e) ----
        float s[8][4];
        #pragma unroll
        for (int jf = 0; jf < 8; jf++)
            #pragma unroll
            for (int c = 0; c < 4; c++) s[jf][c] = 0.f;

        #pragma unroll
        for (int kc = 0; kc < 4; kc++) {
            unsigned bh[4][4];
            #pragma unroll
            for (int jp = 0; jp < 4; jp++) {
                int jrow = jp * 16 + ((sel >> 1) << 3) + r8;
                int ch = 2 * kc + (sel & 1);
                ldsm4(bh[jp], kb + jrow * 128 + ((ch ^ (jrow & 7)) << 4));
            }
            #pragma unroll
            for (int jf = 0; jf < 8; jf++)
                mmaf16(s[jf], aQ[kc],
                       bh[jf >> 1][(jf & 1) * 2], bh[jf >> 1][(jf & 1) * 2 + 1]);
        }

        // ---- causal mask on diagonal tile ----
        if (kt == qt) {
            int rowg = wid * 16 + g;
            #pragma unroll
            for (int jf = 0; jf < 8; jf++) {
                int col = jf * 8 + t2;
                if (col     > rowg)     s[jf][0] = -60000.f;
                if (col + 1 > rowg)     s[jf][1] = -60000.f;
                if (col     > rowg + 8) s[jf][2] = -60000.f;
                if (col + 1 > rowg + 8) s[jf][3] = -60000.f;
            }
        }

        // ---- online softmax: packed-f16 max reduce ----
        float mx0 = -60000.f, mx1 = -60000.f;
        #pragma unroll
        for (int jf = 0; jf < 8; jf++) {
            mx0 = fmaxf(mx0, fmaxf(s[jf][0], s[jf][1]));
            mx1 = fmaxf(mx1, fmaxf(s[jf][2], s[jf][3]));
        }
        unsigned mxp = packh2(mx0, mx1);
        mxp = hmax2u(mxp, __shfl_xor_sync(0xffffffffu, mxp, 1));
        mxp = hmax2u(mxp, __shfl_xor_sync(0xffffffffu, mxp, 2));
        float2 mxf = __half22float2(*(__half2*)&mxp);
        float mn0 = fmaxf(m0, mxf.x), mn1 = fmaxf(m1, mxf.y);
        float a0 = ex2(m0 - mn0), a1 = ex2(m1 - mn1);
        m0 = mn0; m1 = mn1;

        unsigned ph[4][4];
        unsigned P01[8], P23[8];
        #pragma unroll
        for (int jf = 0; jf < 8; jf++) {
            P01[jf] = ex2h2(packh2(s[jf][0] - mn0, s[jf][1] - mn0));
            P23[jf] = ex2h2(packh2(s[jf][2] - mn1, s[jf][3] - mn1));
            int kc = jf >> 1, hi = (jf & 1) * 2;
            ph[kc][hi]     = P01[jf];
            ph[kc][hi + 1] = P23[jf];
        }

        // ---- rescale o, then issue PV mmas BEFORE the l reduction ----
        #pragma unroll
        for (int d = 0; d < 8; d++) {
            o[d][0] *= a0; o[d][1] *= a0;
            o[d][2] *= a1; o[d][3] *= a1;
        }
        #pragma unroll
        for (int kc = 0; kc < 4; kc++) {
            unsigned vh[4][4];
            #pragma unroll
            for (int np = 0; np < 4; np++) {
                int krow = kc * 16 + (lane & 15);
                int ch = np * 2 + (lane >> 4);
                ldsm4t(vh[np], kb + 8192 + krow * 128 + ((ch ^ (krow & 7)) << 4));
            }
            #pragma unroll
            for (int df = 0; df < 8; df++)
                mmaf16(o[df], ph[kc],
                       vh[df >> 1][(df & 1) * 2], vh[df >> 1][(df & 1) * 2 + 1]);
        }

        // ---- deferred l reduction (hidden behind PV mma issue) ----
        unsigned s01 = hadd2u(hadd2u(hadd2u(P01[0], P01[1]), hadd2u(P01[2], P01[3])),
                              hadd2u(hadd2u(P01[4], P01[5]), hadd2u(P01[6], P01[7])));
        unsigned s23 = hadd2u(hadd2u(hadd2u(P23[0], P23[1]), hadd2u(P23[2], P23[3])),
                              hadd2u(hadd2u(P23[4], P23[5]), hadd2u(P23[6], P23[7])));
        float2 f01 = __half22float2(*(__half2*)&s01);
        float2 f23 = __half22float2(*(__half2*)&s23);
        float ps0 = f01.x + f01.y;
        float ps1 = f23.x + f23.y;
        ps0 += __shfl_xor_sync(0xffffffffu, ps0, 1);
        ps0 += __shfl_xor_sync(0xffffffffu, ps0, 2);
        ps1 += __shfl_xor_sync(0xffffffffu, ps1, 1);
        ps1 += __shfl_xor_sync(0xffffffffu, ps1, 2);
        l0 = l0 * a0 + ps0;
        l1 = l1 * a1 + ps1;
    }

    // ---- epilogue: normalize, fp16 out ----
    float inv0 = 1.f / l0, inv1 = 1.f / l1;
    size_t row0 = qrow0 + wid * 16 + g;
    #pragma unroll
    for (int df = 0; df < 8; df++) {
        int col = h * ND + df * 8 + t2;
        *(__half2*)(g_aoh + row0 * NHD + col) =
            __floats2half2_rn(o[df][0] * inv0, o[df][1] * inv0);
        *(__half2*)(g_aoh + (row0 + 8) * NHD + col) =
            __floats2half2_rn(o[df][2] * inv1, o[df][3] * inv1);
    }
}

// ---------------------------------------------------------------------------
// Launch
// ---------------------------------------------------------------------------
extern "C" void kernel_launch(void* const* d_in, const int* in_sizes, int n_in,
                              void* d_out, int out_size) {
    const float* x    = (const float*)d_in[0];
    const float* ln_g = (const float*)d_in[1];
    const float* ln_b = (const float*)d_in[2];
    const float* wq   = (const float*)d_in[3];
    const float* bq   = (const float*)d_in[4];
    const float* wk   = (const float*)d_in[5];
    const float* bk   = (const float*)d_in[6];
    const float* wv   = (const float*)d_in[7];
    const float* bv   = (const float*)d_in[8];
    const float* wo   = (const float*)d_in[9];
    const float* bo   = (const float*)d_in[10];
    float* out = (float*)d_out;

    __half *xnh, *aoh, *wh;
    cudaGetSymbolAddress((void**)&xnh, g_xnh);
    cudaGetSymbolAddress((void**)&aoh, g_aoh);
    cudaGetSymbolAddress((void**)&wh,  g_wh);

    prep_kernel<<<NM + 4096, 256>>>(x, ln_g, ln_b, wq, wk, wv, wo);

    cudaFuncSetAttribute(gemm_f16<1>,
                         cudaFuncAttributeMaxDynamicSharedMemorySize, 65536);
    cudaFuncSetAttribute(gemm_f16<0>,
                         cudaFuncAttributeMaxDynamicSharedMemorySize, 65536);

    const size_t WN = (size_t)NE * NHD;
    // fused QKV: B rows 0..3071 span g_wh[0..2]
    gemm_f16<1><<<dim3(3 * NHD / 128, NM / 128), 256, 65536>>>(
        xnh, wh, bq, bk, bv, nullptr, nullptr);

    cudaFuncSetAttribute(attn_tc_kernel,
                         cudaFuncAttributeMaxDynamicSharedMemorySize, 40960);
    attn_tc_kernel<<<dim3(NS / 64, NH, NB), 128, 40960>>>();

    gemm_f16<0><<<dim3(NE / 128, NM / 128), 256, 65536>>>(
        aoh, wh + 3 * WN, bo, nullptr, nullptr, x, out);
}